// round 15
// baseline (speedup 1.0000x reference)
#include <cuda_runtime.h>
#include <cuda_fp16.h>
#include <math.h>
#include <stdint.h>

// Problem constants
#define BATCH 4
#define SEQ   2048
#define HID   1024
#define NH    16
#define HD    64
#define MTOT  (BATCH * SEQ)   // 8192
#define GK    1024
#define GN    1024

// Scratch (device globals: no runtime allocation allowed)
__device__ __half g_Q [MTOT * HID];
__device__ __half g_K [MTOT * HID];
__device__ __half g_V [MTOT * HID];
__device__ __half g_AO[MTOT * HID];
// fp16 copies of inputs
__device__ __half g_Xq[MTOT * HID];
__device__ __half g_Xk[MTOT * HID];
__device__ __half g_Xv[MTOT * HID];
__device__ __half g_Wq[HID * HID];
__device__ __half g_Wk[HID * HID];
__device__ __half g_Wv[HID * HID];
__device__ __half g_Wo[HID * HID];

#define SCALE_LOG2E 0.1803368801111f        // 0.125 * log2(e)

__device__ __forceinline__ void mma_f16(float* d, const unsigned* a, const unsigned* b) {
    asm volatile(
        "mma.sync.aligned.m16n8k16.row.col.f32.f16.f16.f32 "
        "{%0,%1,%2,%3}, {%4,%5,%6,%7}, {%8,%9}, {%0,%1,%2,%3};\n"
        : "+f"(d[0]), "+f"(d[1]), "+f"(d[2]), "+f"(d[3])
        : "r"(a[0]), "r"(a[1]), "r"(a[2]), "r"(a[3]),
          "r"(b[0]), "r"(b[1]));
}

__device__ __forceinline__ void cp_async16(void* dst, const void* src) {
    unsigned d = (unsigned)__cvta_generic_to_shared(dst);
    asm volatile("cp.async.cg.shared.global [%0], [%1], 16;\n" :: "r"(d), "l"(src));
}
__device__ __forceinline__ void cp_commit() {
    asm volatile("cp.async.commit_group;\n");
}
template <int N>
__device__ __forceinline__ void cp_wait() {
    asm volatile("cp.async.wait_group %0;\n" :: "n"(N));
}

#define LDSM_X4(R0, R1, R2, R3, ADDR) \
    asm volatile("ldmatrix.sync.aligned.m8n8.x4.shared.b16 {%0,%1,%2,%3}, [%4];" \
        : "=r"(R0), "=r"(R1), "=r"(R2), "=r"(R3) : "r"(ADDR))
#define LDSM_X4T(R0, R1, R2, R3, ADDR) \
    asm volatile("ldmatrix.sync.aligned.m8n8.x4.trans.shared.b16 {%0,%1,%2,%3}, [%4];" \
        : "=r"(R0), "=r"(R1), "=r"(R2), "=r"(R3) : "r"(ADDR))

__device__ __forceinline__ unsigned packh2(float lo, float hi) {
    __half2 h = __floats2half2_rn(lo, hi);
    return *reinterpret_cast<unsigned*>(&h);
}
__device__ __forceinline__ unsigned ex2h2(unsigned x) {
    unsigned r;
    asm("ex2.approx.f16x2 %0, %1;" : "=r"(r) : "r"(x));
    return r;
}
__device__ __forceinline__ unsigned hadd2u(unsigned a, unsigned b) {
    __half2 r = __hadd2(*reinterpret_cast<__half2*>(&a),
                        *reinterpret_cast<__half2*>(&b));
    return *reinterpret_cast<unsigned*>(&r);
}

// ---------------------------------------------------------------------------
// Pre-pass: fp32 -> fp16 (RN), one segmented launch for all 7 tensors.
// ---------------------------------------------------------------------------
#define NX8 (MTOT * HID / 8)   // 1048576
#define NW8 (HID * HID / 8)    // 131072
#define CVT_TOTAL (3 * NX8 + 4 * NW8)

__global__ __launch_bounds__(256) void cvt_all(
    const float* x0, const float* x1, const float* x2,
    const float* w0, const float* w1, const float* w2, const float* w3,
    __half* dx0, __half* dx1, __half* dx2,
    __half* dw0, __half* dw1, __half* dw2, __half* dw3)
{
    int i = blockIdx.x * blockDim.x + threadIdx.x;
    if (i >= CVT_TOTAL) return;
    const float* src;
    __half* dst;
    if (i < 3 * NX8) {
        const int t = i / NX8;
        src = (t == 0) ? x0 : (t == 1) ? x1 : x2;
        dst = (t == 0) ? dx0 : (t == 1) ? dx1 : dx2;
        i -= t * NX8;
    } else {
        int j = i - 3 * NX8;
        const int t = j / NW8;
        src = (t == 0) ? w0 : (t == 1) ? w1 : (t == 2) ? w2 : w3;
        dst = (t == 0) ? dw0 : (t == 1) ? dw1 : (t == 2) ? dw2 : dw3;
        i = j - t * NW8;
    }
    float4 v0 = ((const float4*)src)[2 * i];
    float4 v1 = ((const float4*)src)[2 * i + 1];
    unsigned u[4];
    u[0] = packh2(v0.x, v0.y);
    u[1] = packh2(v0.z, v0.w);
    u[2] = packh2(v1.x, v1.y);
    u[3] = packh2(v1.z, v1.w);
    ((uint4*)dst)[i] = *(uint4*)u;
}

// ---------------------------------------------------------------------------
// FP16 GEMM body: C[M,1024] = A[M,1024] @ W[1024,1024]^T + bias
// 128x128 tile, BK=64 (4 k16 sub-steps per barrier), 8 warps (2x4),
// 3-stage cp.async pipeline (2-deep prefetch), ldmatrix frag loads.
// Stride 72 halves -> conflict-free ldmatrix (4r mod 32 phases distinct).
// Halved barrier count vs BK=32 -> longer MMA runs, higher tensor util.
// ---------------------------------------------------------------------------
#define GSTR   72                          // halves per smem row
#define GSTG_H (2 * 128 * GSTR)            // halves per stage (A+B) = 18432
#define GEMM_SMEM (3 * GSTG_H * 2)         // 110592 bytes

template <bool OUT_FLOAT>
__device__ __forceinline__ void gemm_body(
    const __half* __restrict__ A,
    const __half* __restrict__ W,
    const float* __restrict__ bias,
    void* __restrict__ Cv,
    __half* gsm, int row0, int col0, float oscale)
{
    const uint32_t smU = (uint32_t)__cvta_generic_to_shared(gsm);
    const int tid  = threadIdx.x;
    const int lane = tid & 31;
    const int wid  = tid >> 5;
    const int wr   = wid >> 2;
    const int wc   = wid & 3;
    const int tig  = lane & 3;
    const int grp  = lane >> 2;

    float acc[4][4][4];
#pragma unroll
    for (int mi = 0; mi < 4; mi++)
#pragma unroll
        for (int ni = 0; ni < 4; ni++)
#pragma unroll
            for (int q = 0; q < 4; q++) acc[mi][ni][q] = 0.f;

    // copy mapping: 128 rows x 8 pieces(16B) per matrix = 1024 pieces;
    // thread covers row tid>>1, pieces (tid&1)*32 + {0,8,16,24} halves.
    const int cr = tid >> 1;
    const int cj = (tid & 1) * 32;

    auto issue = [&](int it) {
        __half* As = gsm + (it % 3) * GSTG_H;
        __half* Bs = As + 128 * GSTR;
        const int k0 = it * 64;
        const __half* Ap = A + (size_t)(row0 + cr) * GK + k0 + cj;
        const __half* Wp = W + (size_t)(col0 + cr) * GK + k0 + cj;
#pragma unroll
        for (int k = 0; k < 4; k++) {
            cp_async16(&As[cr * GSTR + cj + k * 8], Ap + k * 8);
            cp_async16(&Bs[cr * GSTR + cj + k * 8], Wp + k * 8);
        }
        cp_commit();
    };

    issue(0); issue(1);

    const int aRow  = (lane & 7) + ((lane >> 3) & 1) * 8;
    const int aKoff = (lane >> 4) << 3;
    const int bRow  = ((lane >> 4) << 3) + (lane & 7);
    const int bKoff = ((lane >> 3) & 1) << 3;

    for (int it = 0; it < 16; it++) {
        if (it < 14) cp_wait<1>(); else cp_wait<0>();
        __syncthreads();

        if (it + 2 < 16) issue(it + 2);

        const uint32_t AcU = smU + ((it % 3) * GSTG_H) * 2;
        const uint32_t BcU = AcU + (128 * GSTR) * 2;

#pragma unroll
        for (int kks = 0; kks < 4; kks++) {
            unsigned af[4][4], bf[4][2];
#pragma unroll
            for (int mi = 0; mi < 4; mi++) {
                LDSM_X4(af[mi][0], af[mi][1], af[mi][2], af[mi][3],
                        AcU + (((wr * 64 + mi * 16 + aRow) * GSTR) + kks * 16 + aKoff) * 2);
            }
#pragma unroll
            for (int nb = 0; nb < 2; nb++) {
                unsigned m0, m1, m2, m3;
                LDSM_X4(m0, m1, m2, m3,
                        BcU + (((wc * 32 + nb * 16 + bRow) * GSTR) + kks * 16 + bKoff) * 2);
                bf[2 * nb][0] = m0; bf[2 * nb][1] = m1;
                bf[2 * nb + 1][0] = m2; bf[2 * nb + 1][1] = m3;
            }
#pragma unroll
            for (int mi = 0; mi < 4; mi++)
#pragma unroll
                for (int ni = 0; ni < 4; ni++)
                    mma_f16(acc[mi][ni], af[mi], bf[ni]);
        }
    }

    // epilogue
#pragma unroll
    for (int mi = 0; mi < 4; mi++) {
        const int r = row0 + wr * 64 + mi * 16 + grp;
#pragma unroll
        for (int ni = 0; ni < 4; ni++) {
            const int c = col0 + wc * 32 + ni * 8 + tig * 2;
            const float b0 = bias[c], b1 = bias[c + 1];
            const float v0 = acc[mi][ni][0] + b0;
            const float v1 = acc[mi][ni][1] + b1;
            const float v2 = acc[mi][ni][2] + b0;
            const float v3 = acc[mi][ni][3] + b1;
            if (OUT_FLOAT) {
                float* C = (float*)Cv;
                float2 w0 = { v0, v1 }, w1 = { v2, v3 };
                *(float2*)(C + (size_t)r * GN + c)       = w0;
                *(float2*)(C + (size_t)(r + 8) * GN + c) = w1;
            } else {
                __half* C = (__half*)Cv;
                *(unsigned*)(C + (size_t)r * GN + c)       = packh2(v0 * oscale, v1 * oscale);
                *(unsigned*)(C + (size_t)(r + 8) * GN + c) = packh2(v2 * oscale, v3 * oscale);
            }
        }
    }
}

// Fused Q/K/V projection GEMMs (blockIdx.z selects tensor). Q pre-scaled.
__global__ __launch_bounds__(256, 2) void gemm_qkv(
    const __half* X0, const __half* X1, const __half* X2,
    const __half* W0, const __half* W1, const __half* W2,
    const float* b0, const float* b1, const float* b2,
    __half* C0, __half* C1, __half* C2)
{
    extern __shared__ __half gsm[];
    const int z = blockIdx.z;
    const __half* A = (z == 0) ? X0 : (z == 1) ? X1 : X2;
    const __half* W = (z == 0) ? W0 : (z == 1) ? W1 : W2;
    const float*  b = (z == 0) ? b0 : (z == 1) ? b1 : b2;
    __half*       C = (z == 0) ? C0 : (z == 1) ? C1 : C2;
    const float oscale = (z == 0) ? SCALE_LOG2E : 1.0f;
    gemm_body<false>(A, W, b, C, gsm, blockIdx.y * 128, blockIdx.x * 128, oscale);
}

// Output projection GEMM (fp32 out)
__global__ __launch_bounds__(256, 2) void gemm_wo(
    const __half* __restrict__ A, const __half* __restrict__ W,
    const float* __restrict__ bias, float* __restrict__ C)
{
    extern __shared__ __half gsm[];
    gemm_body<true>(A, W, bias, C, gsm, blockIdx.y * 128, blockIdx.x * 128, 1.0f);
}

// ---------------------------------------------------------------------------
// FP16 causal flash attention, FA2-style (exp2 domain, Q pre-scaled).
// BM=128 (16 q-rows per warp), BN=64, 8 warps, 4-stage cp.async K/V,
// single barrier per tile, batched ldmatrix, deferred-l softmax.
// ---------------------------------------------------------------------------
#define HSTR    72                          // halves per smem row
#define KV_H    (64 * HSTR)                 // halves per matrix per stage
#define KVSTG_B (2 * KV_H * 2)              // bytes per stage (K+V) = 18432
#define ATT_SMEM (4 * KVSTG_B)              // 73728 bytes

__global__ __launch_bounds__(256, 2) void attn_f16(
    const __half* __restrict__ Q,
    const __half* __restrict__ K,
    const __half* __restrict__ V,
    __half* __restrict__ O)
{
    extern __shared__ __half hsm[];
    const uint32_t smU = (uint32_t)__cvta_generic_to_shared(hsm);

    const int tid  = threadIdx.x;
    const int lane = tid & 31;
    const int wid  = tid >> 5;
    const int tig  = lane & 3;
    const int grp  = lane >> 2;

    const int qi = (gridDim.x - 1) - blockIdx.x;   // heavy blocks first
    const int h  = blockIdx.y;
    const int b  = blockIdx.z;

    const int ktmax = 2 * qi + 1;

    const int c0r = tid >> 2;
    const int j0h = (tid & 3) * 8;

    const __half* Kbase = K + (size_t)b * SEQ * HID + h * HD;
    const __half* Vbase = V + (size_t)b * SEQ * HID + h * HD;

    auto issue = [&](int stage, int kt) {
        __half* Ks = hsm + stage * (2 * KV_H);
        __half* Vs = Ks + KV_H;
        const __half* Kb = Kbase + (size_t)kt * 64 * HID;
        const __half* Vb = Vbase + (size_t)kt * 64 * HID;
        cp_async16(&Ks[c0r * HSTR + j0h],      Kb + (size_t)c0r * HID + j0h);
        cp_async16(&Ks[c0r * HSTR + j0h + 32], Kb + (size_t)c0r * HID + j0h + 32);
        cp_async16(&Vs[c0r * HSTR + j0h],      Vb + (size_t)c0r * HID + j0h);
        cp_async16(&Vs[c0r * HSTR + j0h + 32], Vb + (size_t)c0r * HID + j0h + 32);
        cp_commit();
    };

    issue(0, 0);
    issue(1, (1 <= ktmax) ? 1 : ktmax);
    issue(2, (2 <= ktmax) ? 2 : ktmax);

    const int rowlo = qi * 128 + wid * 16 + grp;
    const __half* Qp = Q + ((size_t)b * SEQ + rowlo) * HID + h * HD;
    unsigned qf[4][4];
#pragma unroll
    for (int kk = 0; kk < 4; kk++) {
        qf[kk][0] = *(const unsigned*)(Qp + kk * 16 + tig * 2);
        qf[kk][1] = *(const unsigned*)(Qp + (size_t)8 * HID + kk * 16 + tig * 2);
        qf[kk][2] = *(const unsigned*)(Qp + kk * 16 + 8 + tig * 2);
        qf[kk][3] = *(const unsigned*)(Qp + (size_t)8 * HID + kk * 16 + 8 + tig * 2);
    }

    const int kRow  = ((lane >> 4) << 3) + (lane & 7);
    const int kKoff = ((lane >> 3) & 1) << 3;
    const int vRow  = lane & 15;
    const int vD    = (lane >> 4) << 3;

    float m_i[2] = { -1e30f, -1e30f };
    float l_p[2] = { 0.f, 0.f };     // per-thread PARTIAL row sums
    float o[8][4];
#pragma unroll
    for (int ni = 0; ni < 8; ni++)
#pragma unroll
        for (int q = 0; q < 4; q++) o[ni][q] = 0.f;

    for (int kt = 0; kt <= ktmax; kt++) {
        if (kt + 2 <= ktmax) cp_wait<2>(); else cp_wait<0>();
        __syncthreads();

        if (kt + 3 <= ktmax) issue((kt + 3) & 3, kt + 3);

        const uint32_t KsU = smU + (kt & 3) * KVSTG_B;
        const uint32_t VsU = KsU + KV_H * 2;

        float s[8][4];
#pragma unroll
        for (int ni = 0; ni < 8; ni++)
#pragma unroll
            for (int q = 0; q < 4; q++) s[ni][q] = 0.f;

#pragma unroll
        for (int kk = 0; kk < 4; kk++) {
            unsigned kf[4][4];
#pragma unroll
            for (int p = 0; p < 4; p++) {
                LDSM_X4(kf[p][0], kf[p][1], kf[p][2], kf[p][3],
                        KsU + ((p * 16 + kRow) * HSTR + kk * 16 + kKoff) * 2);
            }
#pragma unroll
            for (int p = 0; p < 4; p++) {
                unsigned bf0[2] = { kf[p][0], kf[p][1] };
                unsigned bf1[2] = { kf[p][2], kf[p][3] };
                mma_f16(s[2 * p],     qf[kk], bf0);
                mma_f16(s[2 * p + 1], qf[kk], bf1);
            }
        }

        if (kt >= 2 * qi) {
#pragma unroll
            for (int ni = 0; ni < 8; ni++) {
                const int c0 = kt * 64 + ni * 8 + tig * 2;
#pragma unroll
                for (int q = 0; q < 4; q++) {
                    const int row = (q < 2) ? rowlo : rowlo + 8;
                    const int col = c0 + (q & 1);
                    if (col > row) s[ni][q] = -1e30f;
                }
            }
        }

        unsigned ep[8][2];
#pragma unroll
        for (int r = 0; r < 2; r++) {
            const int q0 = 2 * r, q1 = 2 * r + 1;
            float mx = -1e30f;
#pragma unroll
            for (int ni = 0; ni < 8; ni++)
                mx = fmaxf(mx, fmaxf(s[ni][q0], s[ni][q1]));
            mx = fmaxf(mx, __shfl_xor_sync(0xffffffffu, mx, 1));
            mx = fmaxf(mx, __shfl_xor_sync(0xffffffffu, mx, 2));
            const float m_new = fmaxf(m_i[r], mx);
            const float al    = exp2f(m_i[r] - m_new);
#pragma unroll
            for (int ni = 0; ni < 8; ni++)
                ep[ni][r] = ex2h2(packh2(s[ni][q0] - m_new, s[ni][q1] - m_new));
            unsigned t0 = hadd2u(ep[0][r], ep[1][r]);
            unsigned t1 = hadd2u(ep[2][r], ep[3][r]);
            unsigned t2 = hadd2u(ep[4][r], ep[5][r]);
            unsigned t3 = hadd2u(ep[6][r], ep[7][r]);
            unsigned tt = hadd2u(hadd2u(t0, t1), hadd2u(t2, t3));
            float2 fs = __half22float2(*reinterpret_cast<__half2*>(&tt));
            m_i[r] = m_new;
            if (__any_sync(0xffffffffu, al != 1.0f)) {
                l_p[r] = l_p[r] * al + (fs.x + fs.y);
#pragma unroll
                for (int ni = 0; ni < 8; ni++) {
                    o[ni][q0] *= al;
                    o[ni][q1] *= al;
                }
            } else {
                l_p[r] += fs.x + fs.y;
            }
        }

#pragma unroll
        for (int kkm = 0; kkm < 4; kkm++) {
            unsigned a[4];
            a[0] = ep[2 * kkm][0];
            a[1] = ep[2 * kkm][1];
            a[2] = ep[2 * kkm + 1][0];
            a[3] = ep[2 * kkm + 1][1];
            unsigned vf[4][4];
#pragma unroll
            for (int p = 0; p < 4; p++) {
                LDSM_X4T(vf[p][0], vf[p][1], vf[p][2], vf[p][3],
                         VsU + ((kkm * 16 + vRow) * HSTR + p * 16 + vD) * 2);
            }
#pragma unroll
            for (int p = 0; p < 4; p++) {
                unsigned bf0[2] = { vf[p][0], vf[p][1] };
                unsigned bf1[2] = { vf[p][2], vf[p][3] };
                mma_f16(o[2 * p],     a, bf0);
                mma_f16(o[2 * p + 1], a, bf1);
            }
        }
    }

    // epilogue: quad-reduce l partials once, divide, store fp16
    float l0 = l_p[0];
    l0 += __shfl_xor_sync(0xffffffffu, l0, 1);
    l0 += __shfl_xor_sync(0xffffffffu, l0, 2);
    float l1 = l_p[1];
    l1 += __shfl_xor_sync(0xffffffffu, l1, 1);
    l1 += __shfl_xor_sync(0xffffffffu, l1, 2);
    const float inv0 = 1.f / l0;
    const float inv1 = 1.f / l1;
    __half* Ob = O + ((size_t)b * SEQ + rowlo) * HID + h * HD;
#pragma unroll
    for (int ni = 0; ni < 8; ni++) {
        const int d = ni * 8 + tig * 2;
        *(unsigned*)(Ob + d)                    = packh2(o[ni][0] * inv0, o[ni][1] * inv0);
        *(unsigned*)(Ob + (size_t)8 * HID + d)  = packh2(o[ni][2] * inv1, o[ni][3] * inv1);
    }
}

// ---------------------------------------------------------------------------
extern "C" void kernel_launch(void* const* d_in, const int* in_sizes, int n_in,
                              void* d_out, int out_size)
{
    const float* query = (const float*)d_in[0];
    const float* key   = (const float*)d_in[1];
    const float* val   = (const float*)d_in[2];
    // d_in[3] = attn_mask (tril causal) — implemented directly in attn_f16
    const float* Wq = (const float*)d_in[4];
    const float* bq = (const float*)d_in[5];
    const float* Wk = (const float*)d_in[6];
    const float* bk = (const float*)d_in[7];
    const float* Wv = (const float*)d_in[8];
    const float* bv = (const float*)d_in[9];
    const float* Wo = (const float*)d_in[10];
    const float* bo = (const float*)d_in[11];
    float* out = (float*)d_out;

    void *pQ, *pK, *pV, *pAO, *pXq, *pXk, *pXv, *pWq, *pWk, *pWv, *pWo;
    cudaGetSymbolAddress(&pQ,  g_Q);
    cudaGetSymbolAddress(&pK,  g_K);
    cudaGetSymbolAddress(&pV,  g_V);
    cudaGetSymbolAddress(&pAO, g_AO);
    cudaGetSymbolAddress(&pXq, g_Xq);
    cudaGetSymbolAddress(&pXk, g_Xk);
    cudaGetSymbolAddress(&pXv, g_Xv);
    cudaGetSymbolAddress(&pWq, g_Wq);
    cudaGetSymbolAddress(&pWk, g_Wk);
    cudaGetSymbolAddress(&pWv, g_Wv);
    cudaGetSymbolAddress(&pWo, g_Wo);

    cudaFuncSetAttribute(gemm_qkv,
                         cudaFuncAttributeMaxDynamicSharedMemorySize, GEMM_SMEM);
    cudaFuncSetAttribute(gemm_wo,
                         cudaFuncAttributeMaxDynamicSharedMemorySize, GEMM_SMEM);
    cudaFuncSetAttribute(attn_f16,
                         cudaFuncAttributeMaxDynamicSharedMemorySize, ATT_SMEM);

    // pre-pass: convert all 7 inputs to fp16 in ONE launch
    cvt_all<<<(CVT_TOTAL + 255) / 256, 256>>>(
        query, key, val, Wq, Wk, Wv, Wo,
        (__half*)pXq, (__half*)pXk, (__half*)pXv,
        (__half*)pWq, (__half*)pWk, (__half*)pWv, (__half*)pWo);

    const dim3 gqkv(GN / 128, MTOT / 128, 3);  // (8, 64, 3)
    gemm_qkv<<<gqkv, 256, GEMM_SMEM>>>(
        (const __half*)pXq, (const __half*)pXk, (const __half*)pXv,
        (const __half*)pWq, (const __half*)pWk, (const __half*)pWv,
        bq, bk, bv,
        (__half*)pQ, (__half*)pK, (__half*)pV);

    const dim3 agrid(SEQ / 128, NH, BATCH);     // (16, 16, 4)
    attn_f16<<<agrid, 256, ATT_SMEM>>>((const __half*)pQ, (const __half*)pK,
                                       (const __half*)pV, (__half*)pAO);

    const dim3 gwo(GN / 128, MTOT / 128);       // (8, 64)
    gemm_wo<<<gwo, 256, GEMM_SMEM>>>((const __half*)pAO, (const __half*)pWo, bo, out);
}

// round 16
// speedup vs baseline: 1.0309x; 1.0309x over previous
#include <cuda_runtime.h>
#include <cuda_fp16.h>
#include <math.h>
#include <stdint.h>

// Problem constants
#define BATCH 4
#define SEQ   2048
#define HID   1024
#define NH    16
#define HD    64
#define MTOT  (BATCH * SEQ)   // 8192
#define GK    1024
#define GN    1024

// Scratch (device globals: no runtime allocation allowed)
__device__ __half g_Q [MTOT * HID];
__device__ __half g_K [MTOT * HID];
__device__ __half g_V [MTOT * HID];
__device__ __half g_AO[MTOT * HID];
// fp16 copies of inputs
__device__ __half g_Xq[MTOT * HID];
__device__ __half g_Xk[MTOT * HID];
__device__ __half g_Xv[MTOT * HID];
__device__ __half g_Wq[HID * HID];
__device__ __half g_Wk[HID * HID];
__device__ __half g_Wv[HID * HID];
__device__ __half g_Wo[HID * HID];

#define SCALE_LOG2E 0.1803368801111f        // 0.125 * log2(e)

__device__ __forceinline__ void mma_f16(float* d, const unsigned* a, const unsigned* b) {
    asm volatile(
        "mma.sync.aligned.m16n8k16.row.col.f32.f16.f16.f32 "
        "{%0,%1,%2,%3}, {%4,%5,%6,%7}, {%8,%9}, {%0,%1,%2,%3};\n"
        : "+f"(d[0]), "+f"(d[1]), "+f"(d[2]), "+f"(d[3])
        : "r"(a[0]), "r"(a[1]), "r"(a[2]), "r"(a[3]),
          "r"(b[0]), "r"(b[1]));
}

__device__ __forceinline__ void cp_async16(void* dst, const void* src) {
    unsigned d = (unsigned)__cvta_generic_to_shared(dst);
    asm volatile("cp.async.cg.shared.global [%0], [%1], 16;\n" :: "r"(d), "l"(src));
}
__device__ __forceinline__ void cp_commit() {
    asm volatile("cp.async.commit_group;\n");
}
template <int N>
__device__ __forceinline__ void cp_wait() {
    asm volatile("cp.async.wait_group %0;\n" :: "n"(N));
}

#define LDSM_X4(R0, R1, R2, R3, ADDR) \
    asm volatile("ldmatrix.sync.aligned.m8n8.x4.shared.b16 {%0,%1,%2,%3}, [%4];" \
        : "=r"(R0), "=r"(R1), "=r"(R2), "=r"(R3) : "r"(ADDR))
#define LDSM_X4T(R0, R1, R2, R3, ADDR) \
    asm volatile("ldmatrix.sync.aligned.m8n8.x4.trans.shared.b16 {%0,%1,%2,%3}, [%4];" \
        : "=r"(R0), "=r"(R1), "=r"(R2), "=r"(R3) : "r"(ADDR))

__device__ __forceinline__ unsigned packh2(float lo, float hi) {
    __half2 h = __floats2half2_rn(lo, hi);
    return *reinterpret_cast<unsigned*>(&h);
}
__device__ __forceinline__ unsigned ex2h2(unsigned x) {
    unsigned r;
    asm("ex2.approx.f16x2 %0, %1;" : "=r"(r) : "r"(x));
    return r;
}
__device__ __forceinline__ unsigned hadd2u(unsigned a, unsigned b) {
    __half2 r = __hadd2(*reinterpret_cast<__half2*>(&a),
                        *reinterpret_cast<__half2*>(&b));
    return *reinterpret_cast<unsigned*>(&r);
}

// ---------------------------------------------------------------------------
// Pre-pass: fp32 -> fp16 (RN), one segmented launch for all 7 tensors.
// ---------------------------------------------------------------------------
#define NX8 (MTOT * HID / 8)   // 1048576
#define NW8 (HID * HID / 8)    // 131072
#define CVT_TOTAL (3 * NX8 + 4 * NW8)

__global__ __launch_bounds__(256) void cvt_all(
    const float* x0, const float* x1, const float* x2,
    const float* w0, const float* w1, const float* w2, const float* w3,
    __half* dx0, __half* dx1, __half* dx2,
    __half* dw0, __half* dw1, __half* dw2, __half* dw3)
{
    int i = blockIdx.x * blockDim.x + threadIdx.x;
    if (i >= CVT_TOTAL) return;
    const float* src;
    __half* dst;
    if (i < 3 * NX8) {
        const int t = i / NX8;
        src = (t == 0) ? x0 : (t == 1) ? x1 : x2;
        dst = (t == 0) ? dx0 : (t == 1) ? dx1 : dx2;
        i -= t * NX8;
    } else {
        int j = i - 3 * NX8;
        const int t = j / NW8;
        src = (t == 0) ? w0 : (t == 1) ? w1 : (t == 2) ? w2 : w3;
        dst = (t == 0) ? dw0 : (t == 1) ? dw1 : (t == 2) ? dw2 : dw3;
        i = j - t * NW8;
    }
    float4 v0 = ((const float4*)src)[2 * i];
    float4 v1 = ((const float4*)src)[2 * i + 1];
    unsigned u[4];
    u[0] = packh2(v0.x, v0.y);
    u[1] = packh2(v0.z, v0.w);
    u[2] = packh2(v1.x, v1.y);
    u[3] = packh2(v1.z, v1.w);
    ((uint4*)dst)[i] = *(uint4*)u;
}

// ---------------------------------------------------------------------------
// FP16 GEMM body v2: C tile 128x64, BK=32, 8 warps (2x4), warp tile 64x16.
// 4-stage cp.async (proven best), ldmatrix frags, 3 CTAs/SM (24 warps) via
// low register budget (acc = 32 regs/warp, __launch_bounds__(256,3)).
// oscale pre-scales fp16 output (Q).
// ---------------------------------------------------------------------------
#define GSTR   40                              // halves per smem row
#define GAB_ROWS 192                           // 128 A rows + 64 B rows
#define GSTG_H (GAB_ROWS * GSTR)               // halves per stage = 7680
#define GEMM_SMEM (4 * GSTG_H * 2)             // 61440 bytes

template <bool OUT_FLOAT>
__device__ __forceinline__ void gemm_body(
    const __half* __restrict__ A,
    const __half* __restrict__ W,
    const float* __restrict__ bias,
    void* __restrict__ Cv,
    __half* gsm, int row0, int col0, float oscale)
{
    const uint32_t smU = (uint32_t)__cvta_generic_to_shared(gsm);
    const int tid  = threadIdx.x;
    const int lane = tid & 31;
    const int wid  = tid >> 5;
    const int wr   = wid >> 2;        // 0..1 : 64-row chunk
    const int wc   = wid & 3;         // 0..3 : 16-col chunk
    const int tig  = lane & 3;
    const int grp  = lane >> 2;

    float acc[4][2][4];
#pragma unroll
    for (int mi = 0; mi < 4; mi++)
#pragma unroll
        for (int ni = 0; ni < 2; ni++)
#pragma unroll
            for (int q = 0; q < 4; q++) acc[mi][ni][q] = 0.f;

    // copy mapping: 192 rows x 4 pieces(16B) = 768 pieces; 3 per thread.
    auto issue = [&](int it) {
        __half* St = gsm + (it & 3) * GSTG_H;
        const int k0 = it * 32;
#pragma unroll
        for (int pp = 0; pp < 3; pp++) {
            const int p = tid + pp * 256;
            const int r = p >> 2;              // 0..191
            const int j = (p & 3) * 8;
            const __half* src = (r < 128)
                ? A + (size_t)(row0 + r) * GK + k0 + j
                : W + (size_t)(col0 + (r - 128)) * GK + k0 + j;
            cp_async16(&St[r * GSTR + j], src);
        }
        cp_commit();
    };

    issue(0); issue(1); issue(2);

    const int aRow  = (lane & 7) + ((lane >> 3) & 1) * 8;
    const int aKoff = (lane >> 4) << 3;
    const int bRow  = ((lane >> 4) << 3) + (lane & 7);
    const int bKoff = ((lane >> 3) & 1) << 3;

    for (int it = 0; it < 32; it++) {
        if (it < 29) cp_wait<2>(); else cp_wait<0>();
        __syncthreads();

        if (it + 3 < 32) issue(it + 3);

        const uint32_t AcU = smU + ((it & 3) * GSTG_H) * 2;
        const uint32_t BcU = AcU + (128 * GSTR) * 2;

#pragma unroll
        for (int kks = 0; kks < 2; kks++) {
            unsigned af[4][4], bf[2][2];
#pragma unroll
            for (int mi = 0; mi < 4; mi++) {
                LDSM_X4(af[mi][0], af[mi][1], af[mi][2], af[mi][3],
                        AcU + (((wr * 64 + mi * 16 + aRow) * GSTR) + kks * 16 + aKoff) * 2);
            }
            {
                unsigned m0, m1, m2, m3;
                LDSM_X4(m0, m1, m2, m3,
                        BcU + (((wc * 16 + bRow) * GSTR) + kks * 16 + bKoff) * 2);
                bf[0][0] = m0; bf[0][1] = m1;
                bf[1][0] = m2; bf[1][1] = m3;
            }
#pragma unroll
            for (int mi = 0; mi < 4; mi++)
#pragma unroll
                for (int ni = 0; ni < 2; ni++)
                    mma_f16(acc[mi][ni], af[mi], bf[ni]);
        }
    }

    // epilogue
#pragma unroll
    for (int mi = 0; mi < 4; mi++) {
        const int r = row0 + wr * 64 + mi * 16 + grp;
#pragma unroll
        for (int ni = 0; ni < 2; ni++) {
            const int c = col0 + wc * 16 + ni * 8 + tig * 2;
            const float b0 = bias[c], b1 = bias[c + 1];
            const float v0 = acc[mi][ni][0] + b0;
            const float v1 = acc[mi][ni][1] + b1;
            const float v2 = acc[mi][ni][2] + b0;
            const float v3 = acc[mi][ni][3] + b1;
            if (OUT_FLOAT) {
                float* C = (float*)Cv;
                float2 w0 = { v0, v1 }, w1 = { v2, v3 };
                *(float2*)(C + (size_t)r * GN + c)       = w0;
                *(float2*)(C + (size_t)(r + 8) * GN + c) = w1;
            } else {
                __half* C = (__half*)Cv;
                *(unsigned*)(C + (size_t)r * GN + c)       = packh2(v0 * oscale, v1 * oscale);
                *(unsigned*)(C + (size_t)(r + 8) * GN + c) = packh2(v2 * oscale, v3 * oscale);
            }
        }
    }
}

// Fused Q/K/V projection GEMMs (blockIdx.z selects tensor). Q pre-scaled.
__global__ __launch_bounds__(256, 3) void gemm_qkv(
    const __half* X0, const __half* X1, const __half* X2,
    const __half* W0, const __half* W1, const __half* W2,
    const float* b0, const float* b1, const float* b2,
    __half* C0, __half* C1, __half* C2)
{
    extern __shared__ __half gsm[];
    const int z = blockIdx.z;
    const __half* A = (z == 0) ? X0 : (z == 1) ? X1 : X2;
    const __half* W = (z == 0) ? W0 : (z == 1) ? W1 : W2;
    const float*  b = (z == 0) ? b0 : (z == 1) ? b1 : b2;
    __half*       C = (z == 0) ? C0 : (z == 1) ? C1 : C2;
    const float oscale = (z == 0) ? SCALE_LOG2E : 1.0f;
    gemm_body<false>(A, W, b, C, gsm, blockIdx.y * 128, blockIdx.x * 64, oscale);
}

// Output projection GEMM (fp32 out)
__global__ __launch_bounds__(256, 3) void gemm_wo(
    const __half* __restrict__ A, const __half* __restrict__ W,
    const float* __restrict__ bias, float* __restrict__ C)
{
    extern __shared__ __half gsm[];
    gemm_body<true>(A, W, bias, C, gsm, blockIdx.y * 128, blockIdx.x * 64, 1.0f);
}

// ---------------------------------------------------------------------------
// FP16 causal flash attention (unchanged from R14 — best measured 142.9us).
// ---------------------------------------------------------------------------
#define HSTR    72                          // halves per smem row
#define KV_H    (64 * HSTR)                 // halves per matrix per stage
#define KVSTG_B (2 * KV_H * 2)              // bytes per stage (K+V) = 18432
#define ATT_SMEM (4 * KVSTG_B)              // 73728 bytes

__global__ __launch_bounds__(256, 2) void attn_f16(
    const __half* __restrict__ Q,
    const __half* __restrict__ K,
    const __half* __restrict__ V,
    __half* __restrict__ O)
{
    extern __shared__ __half hsm[];
    const uint32_t smU = (uint32_t)__cvta_generic_to_shared(hsm);

    const int tid  = threadIdx.x;
    const int lane = tid & 31;
    const int wid  = tid >> 5;
    const int tig  = lane & 3;
    const int grp  = lane >> 2;

    const int qi = (gridDim.x - 1) - blockIdx.x;   // heavy blocks first
    const int h  = blockIdx.y;
    const int b  = blockIdx.z;

    const int ktmax = 2 * qi + 1;

    const int c0r = tid >> 2;
    const int j0h = (tid & 3) * 8;

    const __half* Kbase = K + (size_t)b * SEQ * HID + h * HD;
    const __half* Vbase = V + (size_t)b * SEQ * HID + h * HD;

    auto issue = [&](int stage, int kt) {
        __half* Ks = hsm + stage * (2 * KV_H);
        __half* Vs = Ks + KV_H;
        const __half* Kb = Kbase + (size_t)kt * 64 * HID;
        const __half* Vb = Vbase + (size_t)kt * 64 * HID;
        cp_async16(&Ks[c0r * HSTR + j0h],      Kb + (size_t)c0r * HID + j0h);
        cp_async16(&Ks[c0r * HSTR + j0h + 32], Kb + (size_t)c0r * HID + j0h + 32);
        cp_async16(&Vs[c0r * HSTR + j0h],      Vb + (size_t)c0r * HID + j0h);
        cp_async16(&Vs[c0r * HSTR + j0h + 32], Vb + (size_t)c0r * HID + j0h + 32);
        cp_commit();
    };

    issue(0, 0);
    issue(1, (1 <= ktmax) ? 1 : ktmax);
    issue(2, (2 <= ktmax) ? 2 : ktmax);

    const int rowlo = qi * 128 + wid * 16 + grp;
    const __half* Qp = Q + ((size_t)b * SEQ + rowlo) * HID + h * HD;
    unsigned qf[4][4];
#pragma unroll
    for (int kk = 0; kk < 4; kk++) {
        qf[kk][0] = *(const unsigned*)(Qp + kk * 16 + tig * 2);
        qf[kk][1] = *(const unsigned*)(Qp + (size_t)8 * HID + kk * 16 + tig * 2);
        qf[kk][2] = *(const unsigned*)(Qp + kk * 16 + 8 + tig * 2);
        qf[kk][3] = *(const unsigned*)(Qp + (size_t)8 * HID + kk * 16 + 8 + tig * 2);
    }

    const int kRow  = ((lane >> 4) << 3) + (lane & 7);
    const int kKoff = ((lane >> 3) & 1) << 3;
    const int vRow  = lane & 15;
    const int vD    = (lane >> 4) << 3;

    float m_i[2] = { -1e30f, -1e30f };
    float l_p[2] = { 0.f, 0.f };     // per-thread PARTIAL row sums
    float o[8][4];
#pragma unroll
    for (int ni = 0; ni < 8; ni++)
#pragma unroll
        for (int q = 0; q < 4; q++) o[ni][q] = 0.f;

    for (int kt = 0; kt <= ktmax; kt++) {
        if (kt + 2 <= ktmax) cp_wait<2>(); else cp_wait<0>();
        __syncthreads();

        if (kt + 3 <= ktmax) issue((kt + 3) & 3, kt + 3);

        const uint32_t KsU = smU + (kt & 3) * KVSTG_B;
        const uint32_t VsU = KsU + KV_H * 2;

        float s[8][4];
#pragma unroll
        for (int ni = 0; ni < 8; ni++)
#pragma unroll
            for (int q = 0; q < 4; q++) s[ni][q] = 0.f;

#pragma unroll
        for (int kk = 0; kk < 4; kk++) {
            unsigned kf[4][4];
#pragma unroll
            for (int p = 0; p < 4; p++) {
                LDSM_X4(kf[p][0], kf[p][1], kf[p][2], kf[p][3],
                        KsU + ((p * 16 + kRow) * HSTR + kk * 16 + kKoff) * 2);
            }
#pragma unroll
            for (int p = 0; p < 4; p++) {
                unsigned bf0[2] = { kf[p][0], kf[p][1] };
                unsigned bf1[2] = { kf[p][2], kf[p][3] };
                mma_f16(s[2 * p],     qf[kk], bf0);
                mma_f16(s[2 * p + 1], qf[kk], bf1);
            }
        }

        if (kt >= 2 * qi) {
#pragma unroll
            for (int ni = 0; ni < 8; ni++) {
                const int c0 = kt * 64 + ni * 8 + tig * 2;
#pragma unroll
                for (int q = 0; q < 4; q++) {
                    const int row = (q < 2) ? rowlo : rowlo + 8;
                    const int col = c0 + (q & 1);
                    if (col > row) s[ni][q] = -1e30f;
                }
            }
        }

        unsigned ep[8][2];
#pragma unroll
        for (int r = 0; r < 2; r++) {
            const int q0 = 2 * r, q1 = 2 * r + 1;
            float mx = -1e30f;
#pragma unroll
            for (int ni = 0; ni < 8; ni++)
                mx = fmaxf(mx, fmaxf(s[ni][q0], s[ni][q1]));
            mx = fmaxf(mx, __shfl_xor_sync(0xffffffffu, mx, 1));
            mx = fmaxf(mx, __shfl_xor_sync(0xffffffffu, mx, 2));
            const float m_new = fmaxf(m_i[r], mx);
            const float al    = exp2f(m_i[r] - m_new);
#pragma unroll
            for (int ni = 0; ni < 8; ni++)
                ep[ni][r] = ex2h2(packh2(s[ni][q0] - m_new, s[ni][q1] - m_new));
            unsigned t0 = hadd2u(ep[0][r], ep[1][r]);
            unsigned t1 = hadd2u(ep[2][r], ep[3][r]);
            unsigned t2 = hadd2u(ep[4][r], ep[5][r]);
            unsigned t3 = hadd2u(ep[6][r], ep[7][r]);
            unsigned tt = hadd2u(hadd2u(t0, t1), hadd2u(t2, t3));
            float2 fs = __half22float2(*reinterpret_cast<__half2*>(&tt));
            m_i[r] = m_new;
            if (__any_sync(0xffffffffu, al != 1.0f)) {
                l_p[r] = l_p[r] * al + (fs.x + fs.y);
#pragma unroll
                for (int ni = 0; ni < 8; ni++) {
                    o[ni][q0] *= al;
                    o[ni][q1] *= al;
                }
            } else {
                l_p[r] += fs.x + fs.y;
            }
        }

#pragma unroll
        for (int kkm = 0; kkm < 4; kkm++) {
            unsigned a[4];
            a[0] = ep[2 * kkm][0];
            a[1] = ep[2 * kkm][1];
            a[2] = ep[2 * kkm + 1][0];
            a[3] = ep[2 * kkm + 1][1];
            unsigned vf[4][4];
#pragma unroll
            for (int p = 0; p < 4; p++) {
                LDSM_X4T(vf[p][0], vf[p][1], vf[p][2], vf[p][3],
                         VsU + ((kkm * 16 + vRow) * HSTR + p * 16 + vD) * 2);
            }
#pragma unroll
            for (int p = 0; p < 4; p++) {
                unsigned bf0[2] = { vf[p][0], vf[p][1] };
                unsigned bf1[2] = { vf[p][2], vf[p][3] };
                mma_f16(o[2 * p],     a, bf0);
                mma_f16(o[2 * p + 1], a, bf1);
            }
        }
    }

    // epilogue: quad-reduce l partials once, divide, store fp16
    float l0 = l_p[0];
    l0 += __shfl_xor_sync(0xffffffffu, l0, 1);
    l0 += __shfl_xor_sync(0xffffffffu, l0, 2);
    float l1 = l_p[1];
    l1 += __shfl_xor_sync(0xffffffffu, l1, 1);
    l1 += __shfl_xor_sync(0xffffffffu, l1, 2);
    const float inv0 = 1.f / l0;
    const float inv1 = 1.f / l1;
    __half* Ob = O + ((size_t)b * SEQ + rowlo) * HID + h * HD;
#pragma unroll
    for (int ni = 0; ni < 8; ni++) {
        const int d = ni * 8 + tig * 2;
        *(unsigned*)(Ob + d)                    = packh2(o[ni][0] * inv0, o[ni][1] * inv0);
        *(unsigned*)(Ob + (size_t)8 * HID + d)  = packh2(o[ni][2] * inv1, o[ni][3] * inv1);
    }
}

// ---------------------------------------------------------------------------
extern "C" void kernel_launch(void* const* d_in, const int* in_sizes, int n_in,
                              void* d_out, int out_size)
{
    const float* query = (const float*)d_in[0];
    const float* key   = (const float*)d_in[1];
    const float* val   = (const float*)d_in[2];
    // d_in[3] = attn_mask (tril causal) — implemented directly in attn_f16
    const float* Wq = (const float*)d_in[4];
    const float* bq = (const float*)d_in[5];
    const float* Wk = (const float*)d_in[6];
    const float* bk = (const float*)d_in[7];
    const float* Wv = (const float*)d_in[8];
    const float* bv = (const float*)d_in[9];
    const float* Wo = (const float*)d_in[10];
    const float* bo = (const float*)d_in[11];
    float* out = (float*)d_out;

    void *pQ, *pK, *pV, *pAO, *pXq, *pXk, *pXv, *pWq, *pWk, *pWv, *pWo;
    cudaGetSymbolAddress(&pQ,  g_Q);
    cudaGetSymbolAddress(&pK,  g_K);
    cudaGetSymbolAddress(&pV,  g_V);
    cudaGetSymbolAddress(&pAO, g_AO);
    cudaGetSymbolAddress(&pXq, g_Xq);
    cudaGetSymbolAddress(&pXk, g_Xk);
    cudaGetSymbolAddress(&pXv, g_Xv);
    cudaGetSymbolAddress(&pWq, g_Wq);
    cudaGetSymbolAddress(&pWk, g_Wk);
    cudaGetSymbolAddress(&pWv, g_Wv);
    cudaGetSymbolAddress(&pWo, g_Wo);

    cudaFuncSetAttribute(gemm_qkv,
                         cudaFuncAttributeMaxDynamicSharedMemorySize, GEMM_SMEM);
    cudaFuncSetAttribute(gemm_wo,
                         cudaFuncAttributeMaxDynamicSharedMemorySize, GEMM_SMEM);
    cudaFuncSetAttribute(attn_f16,
                         cudaFuncAttributeMaxDynamicSharedMemorySize, ATT_SMEM);

    // pre-pass: convert all 7 inputs to fp16 in ONE launch
    cvt_all<<<(CVT_TOTAL + 255) / 256, 256>>>(
        query, key, val, Wq, Wk, Wv, Wo,
        (__half*)pXq, (__half*)pXk, (__half*)pXv,
        (__half*)pWq, (__half*)pWk, (__half*)pWv, (__half*)pWo);

    const dim3 gqkv(GN / 64, MTOT / 128, 3);   // (16, 64, 3)
    gemm_qkv<<<gqkv, 256, GEMM_SMEM>>>(
        (const __half*)pXq, (const __half*)pXk, (const __half*)pXv,
        (const __half*)pWq, (const __half*)pWk, (const __half*)pWv,
        bq, bk, bv,
        (__half*)pQ, (__half*)pK, (__half*)pV);

    const dim3 agrid(SEQ / 128, NH, BATCH);     // (16, 16, 4)
    attn_f16<<<agrid, 256, ATT_SMEM>>>((const __half*)pQ, (const __half*)pK,
                                       (const __half*)pV, (__half*)pAO);

    const dim3 gwo(GN / 64, MTOT / 128);        // (16, 64)
    gemm_wo<<<gwo, 256, GEMM_SMEM>>>((const __half*)pAO, (const __half*)pWo, bo, out);
}

// round 17
// speedup vs baseline: 1.1781x; 1.1428x over previous
#include <cuda_runtime.h>
#include <cuda_fp16.h>
#include <math.h>
#include <stdint.h>

// Problem constants
#define BATCH 4
#define SEQ   2048
#define HID   1024
#define NH    16
#define HD    64
#define MTOT  (BATCH * SEQ)   // 8192
#define GK    1024
#define GN    1024

// Scratch (device globals: no runtime allocation allowed)
__device__ __half g_Q [MTOT * HID];
__device__ __half g_K [MTOT * HID];
__device__ __half g_V [MTOT * HID];
__device__ __half g_AO[MTOT * HID];
// fp16 copies of inputs
__device__ __half g_Xq[MTOT * HID];
__device__ __half g_Xk[MTOT * HID];
__device__ __half g_Xv[MTOT * HID];
__device__ __half g_Wq[HID * HID];
__device__ __half g_Wk[HID * HID];
__device__ __half g_Wv[HID * HID];
__device__ __half g_Wo[HID * HID];

#define SCALE_LOG2E 0.1803368801111f        // 0.125 * log2(e)

__device__ __forceinline__ void mma_f16(float* d, const unsigned* a, const unsigned* b) {
    asm volatile(
        "mma.sync.aligned.m16n8k16.row.col.f32.f16.f16.f32 "
        "{%0,%1,%2,%3}, {%4,%5,%6,%7}, {%8,%9}, {%0,%1,%2,%3};\n"
        : "+f"(d[0]), "+f"(d[1]), "+f"(d[2]), "+f"(d[3])
        : "r"(a[0]), "r"(a[1]), "r"(a[2]), "r"(a[3]),
          "r"(b[0]), "r"(b[1]));
}

__device__ __forceinline__ void cp_async16(void* dst, const void* src) {
    unsigned d = (unsigned)__cvta_generic_to_shared(dst);
    asm volatile("cp.async.cg.shared.global [%0], [%1], 16;\n" :: "r"(d), "l"(src));
}
__device__ __forceinline__ void cp_commit() {
    asm volatile("cp.async.commit_group;\n");
}
template <int N>
__device__ __forceinline__ void cp_wait() {
    asm volatile("cp.async.wait_group %0;\n" :: "n"(N));
}

#define LDSM_X4(R0, R1, R2, R3, ADDR) \
    asm volatile("ldmatrix.sync.aligned.m8n8.x4.shared.b16 {%0,%1,%2,%3}, [%4];" \
        : "=r"(R0), "=r"(R1), "=r"(R2), "=r"(R3) : "r"(ADDR))
#define LDSM_X4T(R0, R1, R2, R3, ADDR) \
    asm volatile("ldmatrix.sync.aligned.m8n8.x4.trans.shared.b16 {%0,%1,%2,%3}, [%4];" \
        : "=r"(R0), "=r"(R1), "=r"(R2), "=r"(R3) : "r"(ADDR))

__device__ __forceinline__ unsigned packh2(float lo, float hi) {
    __half2 h = __floats2half2_rn(lo, hi);
    return *reinterpret_cast<unsigned*>(&h);
}
__device__ __forceinline__ unsigned ex2h2(unsigned x) {
    unsigned r;
    asm("ex2.approx.f16x2 %0, %1;" : "=r"(r) : "r"(x));
    return r;
}
__device__ __forceinline__ unsigned hadd2u(unsigned a, unsigned b) {
    __half2 r = __hadd2(*reinterpret_cast<__half2*>(&a),
                        *reinterpret_cast<__half2*>(&b));
    return *reinterpret_cast<unsigned*>(&r);
}

// ---------------------------------------------------------------------------
// Pre-pass: fp32 -> fp16 (RN), one segmented launch for all 7 tensors.
// ---------------------------------------------------------------------------
#define NX8 (MTOT * HID / 8)   // 1048576
#define NW8 (HID * HID / 8)    // 131072
#define CVT_TOTAL (3 * NX8 + 4 * NW8)

__global__ __launch_bounds__(256) void cvt_all(
    const float* x0, const float* x1, const float* x2,
    const float* w0, const float* w1, const float* w2, const float* w3,
    __half* dx0, __half* dx1, __half* dx2,
    __half* dw0, __half* dw1, __half* dw2, __half* dw3)
{
    int i = blockIdx.x * blockDim.x + threadIdx.x;
    if (i >= CVT_TOTAL) return;
    const float* src;
    __half* dst;
    if (i < 3 * NX8) {
        const int t = i / NX8;
        src = (t == 0) ? x0 : (t == 1) ? x1 : x2;
        dst = (t == 0) ? dx0 : (t == 1) ? dx1 : dx2;
        i -= t * NX8;
    } else {
        int j = i - 3 * NX8;
        const int t = j / NW8;
        src = (t == 0) ? w0 : (t == 1) ? w1 : (t == 2) ? w2 : w3;
        dst = (t == 0) ? dw0 : (t == 1) ? dw1 : (t == 2) ? dw2 : dw3;
        i = j - t * NW8;
    }
    float4 v0 = ((const float4*)src)[2 * i];
    float4 v1 = ((const float4*)src)[2 * i + 1];
    unsigned u[4];
    u[0] = packh2(v0.x, v0.y);
    u[1] = packh2(v0.z, v0.w);
    u[2] = packh2(v1.x, v1.y);
    u[3] = packh2(v1.z, v1.w);
    ((uint4*)dst)[i] = *(uint4*)u;
}

// ---------------------------------------------------------------------------
// FP16 GEMM body: C[M,1024] = A[M,1024] @ W[1024,1024]^T + bias
// 128x128 tile, BK=32, 8 warps (2x4), FIVE-stage cp.async pipeline
// (prefetch depth 4 — covers L2 latency), ldmatrix frag loads.
// Single __syncthreads per k-iteration. oscale pre-scales fp16 output (Q).
// ---------------------------------------------------------------------------
#define GSTR   40                          // halves per smem row
#define GSTG_H (2 * 128 * GSTR)            // halves per stage (A+B) = 10240
#define GSTAGES 5
#define GEMM_SMEM (GSTAGES * GSTG_H * 2)   // 102400 bytes

template <bool OUT_FLOAT>
__device__ __forceinline__ void gemm_body(
    const __half* __restrict__ A,
    const __half* __restrict__ W,
    const float* __restrict__ bias,
    void* __restrict__ Cv,
    __half* gsm, int row0, int col0, float oscale)
{
    const uint32_t smU = (uint32_t)__cvta_generic_to_shared(gsm);
    const int tid  = threadIdx.x;
    const int lane = tid & 31;
    const int wid  = tid >> 5;
    const int wr   = wid >> 2;
    const int wc   = wid & 3;
    const int tig  = lane & 3;
    const int grp  = lane >> 2;

    float acc[4][4][4];
#pragma unroll
    for (int mi = 0; mi < 4; mi++)
#pragma unroll
        for (int ni = 0; ni < 4; ni++)
#pragma unroll
            for (int q = 0; q < 4; q++) acc[mi][ni][q] = 0.f;

    const int r0c = tid >> 2, j0 = (tid & 3) * 8;
    const int r1c = (tid + 256) >> 2, j1 = ((tid + 256) & 3) * 8;

    auto issue = [&](int it) {
        __half* As = gsm + (it % GSTAGES) * GSTG_H;
        __half* Bs = As + 128 * GSTR;
        const int k0 = it * 32;
        cp_async16(&As[r0c * GSTR + j0], A + (size_t)(row0 + r0c) * GK + k0 + j0);
        cp_async16(&As[r1c * GSTR + j1], A + (size_t)(row0 + r1c) * GK + k0 + j1);
        cp_async16(&Bs[r0c * GSTR + j0], W + (size_t)(col0 + r0c) * GK + k0 + j0);
        cp_async16(&Bs[r1c * GSTR + j1], W + (size_t)(col0 + r1c) * GK + k0 + j1);
        cp_commit();
    };

    issue(0); issue(1); issue(2); issue(3);

    const int aRow  = (lane & 7) + ((lane >> 3) & 1) * 8;
    const int aKoff = (lane >> 4) << 3;
    const int bRow  = ((lane >> 4) << 3) + (lane & 7);
    const int bKoff = ((lane >> 3) & 1) << 3;

    for (int it = 0; it < 32; it++) {
        if (it < 29) cp_wait<3>(); else cp_wait<0>();
        __syncthreads();

        if (it + 4 < 32) issue(it + 4);

        const uint32_t AcU = smU + ((it % GSTAGES) * GSTG_H) * 2;
        const uint32_t BcU = AcU + (128 * GSTR) * 2;

#pragma unroll
        for (int kks = 0; kks < 2; kks++) {
            unsigned af[4][4], bf[4][2];
#pragma unroll
            for (int mi = 0; mi < 4; mi++) {
                LDSM_X4(af[mi][0], af[mi][1], af[mi][2], af[mi][3],
                        AcU + (((wr * 64 + mi * 16 + aRow) * GSTR) + kks * 16 + aKoff) * 2);
            }
#pragma unroll
            for (int nb = 0; nb < 2; nb++) {
                unsigned m0, m1, m2, m3;
                LDSM_X4(m0, m1, m2, m3,
                        BcU + (((wc * 32 + nb * 16 + bRow) * GSTR) + kks * 16 + bKoff) * 2);
                bf[2 * nb][0] = m0; bf[2 * nb][1] = m1;
                bf[2 * nb + 1][0] = m2; bf[2 * nb + 1][1] = m3;
            }
#pragma unroll
            for (int mi = 0; mi < 4; mi++)
#pragma unroll
                for (int ni = 0; ni < 4; ni++)
                    mma_f16(acc[mi][ni], af[mi], bf[ni]);
        }
    }

    // epilogue
#pragma unroll
    for (int mi = 0; mi < 4; mi++) {
        const int r = row0 + wr * 64 + mi * 16 + grp;
#pragma unroll
        for (int ni = 0; ni < 4; ni++) {
            const int c = col0 + wc * 32 + ni * 8 + tig * 2;
            const float b0 = bias[c], b1 = bias[c + 1];
            const float v0 = acc[mi][ni][0] + b0;
            const float v1 = acc[mi][ni][1] + b1;
            const float v2 = acc[mi][ni][2] + b0;
            const float v3 = acc[mi][ni][3] + b1;
            if (OUT_FLOAT) {
                float* C = (float*)Cv;
                float2 w0 = { v0, v1 }, w1 = { v2, v3 };
                *(float2*)(C + (size_t)r * GN + c)       = w0;
                *(float2*)(C + (size_t)(r + 8) * GN + c) = w1;
            } else {
                __half* C = (__half*)Cv;
                *(unsigned*)(C + (size_t)r * GN + c)       = packh2(v0 * oscale, v1 * oscale);
                *(unsigned*)(C + (size_t)(r + 8) * GN + c) = packh2(v2 * oscale, v3 * oscale);
            }
        }
    }
}

// Fused Q/K/V projection GEMMs (blockIdx.z selects tensor). Q pre-scaled.
__global__ __launch_bounds__(256, 2) void gemm_qkv(
    const __half* X0, const __half* X1, const __half* X2,
    const __half* W0, const __half* W1, const __half* W2,
    const float* b0, const float* b1, const float* b2,
    __half* C0, __half* C1, __half* C2)
{
    extern __shared__ __half gsm[];
    const int z = blockIdx.z;
    const __half* A = (z == 0) ? X0 : (z == 1) ? X1 : X2;
    const __half* W = (z == 0) ? W0 : (z == 1) ? W1 : W2;
    const float*  b = (z == 0) ? b0 : (z == 1) ? b1 : b2;
    __half*       C = (z == 0) ? C0 : (z == 1) ? C1 : C2;
    const float oscale = (z == 0) ? SCALE_LOG2E : 1.0f;
    gemm_body<false>(A, W, b, C, gsm, blockIdx.y * 128, blockIdx.x * 128, oscale);
}

// Output projection GEMM (fp32 out)
__global__ __launch_bounds__(256, 2) void gemm_wo(
    const __half* __restrict__ A, const __half* __restrict__ W,
    const float* __restrict__ bias, float* __restrict__ C)
{
    extern __shared__ __half gsm[];
    gemm_body<true>(A, W, bias, C, gsm, blockIdx.y * 128, blockIdx.x * 128, 1.0f);
}

// ---------------------------------------------------------------------------
// FP16 causal flash attention (R14 config — best measured 142.9us).
// BM=128 (16 q-rows per warp), BN=64, 8 warps, 4-stage cp.async K/V,
// single barrier per tile, batched ldmatrix, deferred-l softmax.
// ---------------------------------------------------------------------------
#define HSTR    72                          // halves per smem row
#define KV_H    (64 * HSTR)                 // halves per matrix per stage
#define KVSTG_B (2 * KV_H * 2)              // bytes per stage (K+V) = 18432
#define ATT_SMEM (4 * KVSTG_B)              // 73728 bytes

__global__ __launch_bounds__(256, 2) void attn_f16(
    const __half* __restrict__ Q,
    const __half* __restrict__ K,
    const __half* __restrict__ V,
    __half* __restrict__ O)
{
    extern __shared__ __half hsm[];
    const uint32_t smU = (uint32_t)__cvta_generic_to_shared(hsm);

    const int tid  = threadIdx.x;
    const int lane = tid & 31;
    const int wid  = tid >> 5;
    const int tig  = lane & 3;
    const int grp  = lane >> 2;

    const int qi = (gridDim.x - 1) - blockIdx.x;   // heavy blocks first
    const int h  = blockIdx.y;
    const int b  = blockIdx.z;

    const int ktmax = 2 * qi + 1;

    const int c0r = tid >> 2;
    const int j0h = (tid & 3) * 8;

    const __half* Kbase = K + (size_t)b * SEQ * HID + h * HD;
    const __half* Vbase = V + (size_t)b * SEQ * HID + h * HD;

    auto issue = [&](int stage, int kt) {
        __half* Ks = hsm + stage * (2 * KV_H);
        __half* Vs = Ks + KV_H;
        const __half* Kb = Kbase + (size_t)kt * 64 * HID;
        const __half* Vb = Vbase + (size_t)kt * 64 * HID;
        cp_async16(&Ks[c0r * HSTR + j0h],      Kb + (size_t)c0r * HID + j0h);
        cp_async16(&Ks[c0r * HSTR + j0h + 32], Kb + (size_t)c0r * HID + j0h + 32);
        cp_async16(&Vs[c0r * HSTR + j0h],      Vb + (size_t)c0r * HID + j0h);
        cp_async16(&Vs[c0r * HSTR + j0h + 32], Vb + (size_t)c0r * HID + j0h + 32);
        cp_commit();
    };

    issue(0, 0);
    issue(1, (1 <= ktmax) ? 1 : ktmax);
    issue(2, (2 <= ktmax) ? 2 : ktmax);

    const int rowlo = qi * 128 + wid * 16 + grp;
    const __half* Qp = Q + ((size_t)b * SEQ + rowlo) * HID + h * HD;
    unsigned qf[4][4];
#pragma unroll
    for (int kk = 0; kk < 4; kk++) {
        qf[kk][0] = *(const unsigned*)(Qp + kk * 16 + tig * 2);
        qf[kk][1] = *(const unsigned*)(Qp + (size_t)8 * HID + kk * 16 + tig * 2);
        qf[kk][2] = *(const unsigned*)(Qp + kk * 16 + 8 + tig * 2);
        qf[kk][3] = *(const unsigned*)(Qp + (size_t)8 * HID + kk * 16 + 8 + tig * 2);
    }

    const int kRow  = ((lane >> 4) << 3) + (lane & 7);
    const int kKoff = ((lane >> 3) & 1) << 3;
    const int vRow  = lane & 15;
    const int vD    = (lane >> 4) << 3;

    float m_i[2] = { -1e30f, -1e30f };
    float l_p[2] = { 0.f, 0.f };     // per-thread PARTIAL row sums
    float o[8][4];
#pragma unroll
    for (int ni = 0; ni < 8; ni++)
#pragma unroll
        for (int q = 0; q < 4; q++) o[ni][q] = 0.f;

    for (int kt = 0; kt <= ktmax; kt++) {
        if (kt + 2 <= ktmax) cp_wait<2>(); else cp_wait<0>();
        __syncthreads();

        if (kt + 3 <= ktmax) issue((kt + 3) & 3, kt + 3);

        const uint32_t KsU = smU + (kt & 3) * KVSTG_B;
        const uint32_t VsU = KsU + KV_H * 2;

        float s[8][4];
#pragma unroll
        for (int ni = 0; ni < 8; ni++)
#pragma unroll
            for (int q = 0; q < 4; q++) s[ni][q] = 0.f;

#pragma unroll
        for (int kk = 0; kk < 4; kk++) {
            unsigned kf[4][4];
#pragma unroll
            for (int p = 0; p < 4; p++) {
                LDSM_X4(kf[p][0], kf[p][1], kf[p][2], kf[p][3],
                        KsU + ((p * 16 + kRow) * HSTR + kk * 16 + kKoff) * 2);
            }
#pragma unroll
            for (int p = 0; p < 4; p++) {
                unsigned bf0[2] = { kf[p][0], kf[p][1] };
                unsigned bf1[2] = { kf[p][2], kf[p][3] };
                mma_f16(s[2 * p],     qf[kk], bf0);
                mma_f16(s[2 * p + 1], qf[kk], bf1);
            }
        }

        if (kt >= 2 * qi) {
#pragma unroll
            for (int ni = 0; ni < 8; ni++) {
                const int c0 = kt * 64 + ni * 8 + tig * 2;
#pragma unroll
                for (int q = 0; q < 4; q++) {
                    const int row = (q < 2) ? rowlo : rowlo + 8;
                    const int col = c0 + (q & 1);
                    if (col > row) s[ni][q] = -1e30f;
                }
            }
        }

        unsigned ep[8][2];
#pragma unroll
        for (int r = 0; r < 2; r++) {
            const int q0 = 2 * r, q1 = 2 * r + 1;
            float mx = -1e30f;
#pragma unroll
            for (int ni = 0; ni < 8; ni++)
                mx = fmaxf(mx, fmaxf(s[ni][q0], s[ni][q1]));
            mx = fmaxf(mx, __shfl_xor_sync(0xffffffffu, mx, 1));
            mx = fmaxf(mx, __shfl_xor_sync(0xffffffffu, mx, 2));
            const float m_new = fmaxf(m_i[r], mx);
            const float al    = exp2f(m_i[r] - m_new);
#pragma unroll
            for (int ni = 0; ni < 8; ni++)
                ep[ni][r] = ex2h2(packh2(s[ni][q0] - m_new, s[ni][q1] - m_new));
            unsigned t0 = hadd2u(ep[0][r], ep[1][r]);
            unsigned t1 = hadd2u(ep[2][r], ep[3][r]);
            unsigned t2 = hadd2u(ep[4][r], ep[5][r]);
            unsigned t3 = hadd2u(ep[6][r], ep[7][r]);
            unsigned tt = hadd2u(hadd2u(t0, t1), hadd2u(t2, t3));
            float2 fs = __half22float2(*reinterpret_cast<__half2*>(&tt));
            m_i[r] = m_new;
            if (__any_sync(0xffffffffu, al != 1.0f)) {
                l_p[r] = l_p[r] * al + (fs.x + fs.y);
#pragma unroll
                for (int ni = 0; ni < 8; ni++) {
                    o[ni][q0] *= al;
                    o[ni][q1] *= al;
                }
            } else {
                l_p[r] += fs.x + fs.y;
            }
        }

#pragma unroll
        for (int kkm = 0; kkm < 4; kkm++) {
            unsigned a[4];
            a[0] = ep[2 * kkm][0];
            a[1] = ep[2 * kkm][1];
            a[2] = ep[2 * kkm + 1][0];
            a[3] = ep[2 * kkm + 1][1];
            unsigned vf[4][4];
#pragma unroll
            for (int p = 0; p < 4; p++) {
                LDSM_X4T(vf[p][0], vf[p][1], vf[p][2], vf[p][3],
                         VsU + ((kkm * 16 + vRow) * HSTR + p * 16 + vD) * 2);
            }
#pragma unroll
            for (int p = 0; p < 4; p++) {
                unsigned bf0[2] = { vf[p][0], vf[p][1] };
                unsigned bf1[2] = { vf[p][2], vf[p][3] };
                mma_f16(o[2 * p],     a, bf0);
                mma_f16(o[2 * p + 1], a, bf1);
            }
        }
    }

    // epilogue: quad-reduce l partials once, divide, store fp16
    float l0 = l_p[0];
    l0 += __shfl_xor_sync(0xffffffffu, l0, 1);
    l0 += __shfl_xor_sync(0xffffffffu, l0, 2);
    float l1 = l_p[1];
    l1 += __shfl_xor_sync(0xffffffffu, l1, 1);
    l1 += __shfl_xor_sync(0xffffffffu, l1, 2);
    const float inv0 = 1.f / l0;
    const float inv1 = 1.f / l1;
    __half* Ob = O + ((size_t)b * SEQ + rowlo) * HID + h * HD;
#pragma unroll
    for (int ni = 0; ni < 8; ni++) {
        const int d = ni * 8 + tig * 2;
        *(unsigned*)(Ob + d)                    = packh2(o[ni][0] * inv0, o[ni][1] * inv0);
        *(unsigned*)(Ob + (size_t)8 * HID + d)  = packh2(o[ni][2] * inv1, o[ni][3] * inv1);
    }
}

// ---------------------------------------------------------------------------
extern "C" void kernel_launch(void* const* d_in, const int* in_sizes, int n_in,
                              void* d_out, int out_size)
{
    const float* query = (const float*)d_in[0];
    const float* key   = (const float*)d_in[1];
    const float* val   = (const float*)d_in[2];
    // d_in[3] = attn_mask (tril causal) — implemented directly in attn_f16
    const float* Wq = (const float*)d_in[4];
    const float* bq = (const float*)d_in[5];
    const float* Wk = (const float*)d_in[6];
    const float* bk = (const float*)d_in[7];
    const float* Wv = (const float*)d_in[8];
    const float* bv = (const float*)d_in[9];
    const float* Wo = (const float*)d_in[10];
    const float* bo = (const float*)d_in[11];
    float* out = (float*)d_out;

    void *pQ, *pK, *pV, *pAO, *pXq, *pXk, *pXv, *pWq, *pWk, *pWv, *pWo;
    cudaGetSymbolAddress(&pQ,  g_Q);
    cudaGetSymbolAddress(&pK,  g_K);
    cudaGetSymbolAddress(&pV,  g_V);
    cudaGetSymbolAddress(&pAO, g_AO);
    cudaGetSymbolAddress(&pXq, g_Xq);
    cudaGetSymbolAddress(&pXk, g_Xk);
    cudaGetSymbolAddress(&pXv, g_Xv);
    cudaGetSymbolAddress(&pWq, g_Wq);
    cudaGetSymbolAddress(&pWk, g_Wk);
    cudaGetSymbolAddress(&pWv, g_Wv);
    cudaGetSymbolAddress(&pWo, g_Wo);

    cudaFuncSetAttribute(gemm_qkv,
                         cudaFuncAttributeMaxDynamicSharedMemorySize, GEMM_SMEM);
    cudaFuncSetAttribute(gemm_wo,
                         cudaFuncAttributeMaxDynamicSharedMemorySize, GEMM_SMEM);
    cudaFuncSetAttribute(attn_f16,
                         cudaFuncAttributeMaxDynamicSharedMemorySize, ATT_SMEM);

    // pre-pass: convert all 7 inputs to fp16 in ONE launch
    cvt_all<<<(CVT_TOTAL + 255) / 256, 256>>>(
        query, key, val, Wq, Wk, Wv, Wo,
        (__half*)pXq, (__half*)pXk, (__half*)pXv,
        (__half*)pWq, (__half*)pWk, (__half*)pWv, (__half*)pWo);

    const dim3 gqkv(GN / 128, MTOT / 128, 3);  // (8, 64, 3)
    gemm_qkv<<<gqkv, 256, GEMM_SMEM>>>(
        (const __half*)pXq, (const __half*)pXk, (const __half*)pXv,
        (const __half*)pWq, (const __half*)pWk, (const __half*)pWv,
        bq, bk, bv,
        (__half*)pQ, (__half*)pK, (__half*)pV);

    const dim3 agrid(SEQ / 128, NH, BATCH);     // (16, 16, 4)
    attn_f16<<<agrid, 256, ATT_SMEM>>>((const __half*)pQ, (const __half*)pK,
                                       (const __half*)pV, (__half*)pAO);

    const dim3 gwo(GN / 128, MTOT / 128);       // (8, 64)
    gemm_wo<<<gwo, 256, GEMM_SMEM>>>((const __half*)pAO, (const __half*)pWo, bo, out);
}